// round 15
// baseline (speedup 1.0000x reference)
#include <cuda_runtime.h>
#include <cuda_fp16.h>
#include <math.h>
#include <stdint.h>

#define BB 8
#define SS 2048
#define DD 768

// Scratch (allocation-free __device__ globals). fp16 operands everywhere.
__device__ __half g_QK[BB * SS * (2 * DD)];  // Q|K interleaved: [B*S, 1536]
__device__ __half g_VT[BB * DD * SS];        // V transposed per batch: [B][D][S]
__device__ __half g_Xh[BB * SS * DD];        // x in fp16
__device__ __half g_Wh[3 * DD * DD];         // Wq|Wk|Wv in fp16
__device__ __half g_At[BB * SS * SS];        // exp(scores) in fp16 (unnormalized)
__device__ float  g_rowsum[BB * SS];         // per-row sums of exp(scores)
// Fine-grained completion counters:
__device__ int    g_cnt_qkrow[BB * 16];      // per QK m-block (target 12)
__device__ int    g_cnt_vtrow[BB * 6];       // per VT d-block (target 16)
__device__ int    g_cnt_scrow[BB * 16];      // per scores row-block (target 16)

__device__ __forceinline__ uint32_t swz(uint32_t byte) {
    return byte ^ ((byte >> 3) & 0x70);
}
__device__ __forceinline__ void ldsm4(uint32_t& r0, uint32_t& r1,
                                      uint32_t& r2, uint32_t& r3, uint32_t addr) {
    asm volatile("ldmatrix.sync.aligned.m8n8.x4.shared.b16 {%0,%1,%2,%3}, [%4];"
                 : "=r"(r0), "=r"(r1), "=r"(r2), "=r"(r3) : "r"(addr));
}
__device__ __forceinline__ void mma16(float* c, const uint32_t* a,
                                      uint32_t b0, uint32_t b1) {
    asm volatile(
        "mma.sync.aligned.m16n8k16.row.col.f32.f16.f16.f32 "
        "{%0,%1,%2,%3}, {%4,%5,%6,%7}, {%8,%9}, {%0,%1,%2,%3};"
        : "+f"(c[0]), "+f"(c[1]), "+f"(c[2]), "+f"(c[3])
        : "r"(a[0]), "r"(a[1]), "r"(a[2]), "r"(a[3]), "r"(b0), "r"(b1));
}
__device__ __forceinline__ void cp16(uint32_t dst, const void* src) {
    asm volatile("cp.async.cg.shared.global [%0], [%1], 16;" :: "r"(dst), "l"(src));
}
__device__ __forceinline__ void cp_commit() {
    asm volatile("cp.async.commit_group;" ::: "memory");
}
__device__ __forceinline__ void cp_wait1() {
    asm volatile("cp.async.wait_group 1;" ::: "memory");
}
__device__ __forceinline__ void spin_until(int* cnt, int target) {
    while (atomicAdd(cnt, 0) < target) __nanosleep(128);
}

// ---------------------------------------------------------------------------
// Fused elementwise fp32 -> fp16 over x, Wq, Wk, Wv + rowsum/counter zeroing.
// ---------------------------------------------------------------------------
__device__ __forceinline__ uint2 cvt4(float4 v) {
    __half2 h01 = __floats2half2_rn(v.x, v.y);
    __half2 h23 = __floats2half2_rn(v.z, v.w);
    uint2 u;
    u.x = *reinterpret_cast<uint32_t*>(&h01);
    u.y = *reinterpret_cast<uint32_t*>(&h23);
    return u;
}
__global__ __launch_bounds__(256) void cvt_all_kernel(
    const float4* __restrict__ x,
    const float4* __restrict__ wq, const float4* __restrict__ wk,
    const float4* __restrict__ wv,
    uint2* __restrict__ xh, uint2* __restrict__ wh,
    float4* __restrict__ rz, int n4x, int n4w)
{
    int i = blockIdx.x * 256 + threadIdx.x;
    if (i < (BB * SS) / 4)
        rz[i] = make_float4(0.f, 0.f, 0.f, 0.f);
    if (i < BB * 16) { g_cnt_qkrow[i] = 0; g_cnt_scrow[i] = 0; }
    if (i < BB * 6)  { g_cnt_vtrow[i] = 0; }
    if (i < n4x) {
        xh[i] = cvt4(x[i]);
    } else {
        int j = i - n4x;
        if (j < n4w)               wh[j] = cvt4(wq[j]);
        else if (j < 2 * n4w)      wh[j] = cvt4(wk[j - n4w]);
        else if (j < 3 * n4w)      wh[j] = cvt4(wv[j - 2 * n4w]);
    }
}

// ---------------------------------------------------------------------------
// GEMM body (R7-validated mainloop): TN fp16, acc = sum_k A[m,k]*B[n,k].
// Block tile 128x128, K-chunks of 64 (128B SW128 rows), 3-stage cp.async,
// 8 warps (4m x 2n), warp tile 32x64 of m16n8k16 MMAs.
// Epilogues:
//   OUT=1 : C fp16 = acc*alpha                         (projections)
//   OUT=2 : C fp32 = acc * (1/rs[row])                 (AV)
//   OUT=3 : e=expf(acc*alpha); C2 fp16 = e; atomicAdd rsum[row]  (scores)
// ---------------------------------------------------------------------------
#define CK 64
#define STG_BYTES 32768            // A 16KB + B 16KB
#define DYN_SMEM  (3 * STG_BYTES)  // 98304; 2 CTAs/SM

template <int OUT>
__device__ __forceinline__ void gemm_body(
    const __half* __restrict__ A, const __half* __restrict__ B,
    void* __restrict__ Cv, int N, int K, int lda, int ldb,
    float alpha, int m0, int n0,
    const float* __restrict__ rs, __half* __restrict__ C2,
    float* __restrict__ rsum)
{
    extern __shared__ __align__(1024) uint8_t dynsm[];

    const int tid  = threadIdx.x;
    const int lane = tid & 31;
    const int warp = tid >> 5;
    const int wm   = warp >> 1;
    const int wn   = warp & 1;

    const uint32_t smbase = (uint32_t)__cvta_generic_to_shared(dynsm);

    const int r0  = tid >> 3;
    const int gg  = tid & 7;
    const uint32_t g16 = (uint32_t)gg * 16;

    const __half* pa[4]; uint32_t oa[4];
    const __half* pb[4]; uint32_t ob[4];
    #pragma unroll
    for (int j = 0; j < 4; j++) {
        int row = r0 + 32 * j;
        pa[j] = A + (long long)(m0 + row) * lda + gg * 8;
        oa[j] = swz((uint32_t)row * 128 + g16);
        pb[j] = B + (long long)(n0 + row) * ldb + gg * 8;
        ob[j] = swz((uint32_t)row * 128 + g16) + 16384;
    }

    const int KT = K / CK;

    #define FILL(t) do {                                          \
        uint32_t sb = smbase + ((t) % 3) * STG_BYTES;             \
        int ko = (t) * CK;                                        \
        _Pragma("unroll")                                         \
        for (int j = 0; j < 4; j++) {                             \
            cp16(sb + oa[j], pa[j] + ko);                         \
            cp16(sb + ob[j], pb[j] + ko);                         \
        }                                                         \
    } while (0)

    FILL(0); cp_commit();
    FILL(1); cp_commit();

    float acc[2][8][4] = {};

    const int lrow = (lane & 7) + ((lane >> 3) & 1) * 8;
    const uint32_t glo = (uint32_t)(lane >> 4) * 16;
    uint32_t aoff[2], boff[4];
    #pragma unroll
    for (int mi = 0; mi < 2; mi++)
        aoff[mi] = swz((uint32_t)((wm * 32 + mi * 16 + lrow) * 128)) ^ glo;
    #pragma unroll
    for (int l = 0; l < 4; l++)
        boff[l] = (swz((uint32_t)((wn * 64 + l * 16 + lrow) * 128)) ^ glo) + 16384;

    for (int i = 0; i < KT; i++) {
        cp_wait1();
        __syncthreads();
        if (i + 2 < KT) FILL(i + 2);
        cp_commit();

        const uint32_t stage = smbase + (i % 3) * STG_BYTES;

        #pragma unroll
        for (int ks = 0; ks < 4; ks++) {
            const uint32_t gx = (uint32_t)(ks * 32);
            uint32_t a[2][4], b[4][4];
            #pragma unroll
            for (int mi = 0; mi < 2; mi++)
                ldsm4(a[mi][0], a[mi][1], a[mi][2], a[mi][3],
                      stage + (aoff[mi] ^ gx));
            #pragma unroll
            for (int l = 0; l < 4; l++)
                ldsm4(b[l][0], b[l][1], b[l][2], b[l][3],
                      stage + (boff[l] ^ gx));
            #pragma unroll
            for (int mi = 0; mi < 2; mi++)
                #pragma unroll
                for (int j = 0; j < 8; j++) {
                    const int l = j >> 1, o = j & 1;
                    mma16(acc[mi][j], a[mi], b[l][o], b[l][o + 2]);
                }
        }
    }
    #undef FILL

    const int rr0 = m0 + wm * 32 + (lane >> 2);
    const int cc0 = n0 + wn * 64 + (lane & 3) * 2;

    if (OUT == 1) {
        __half* C = (__half*)Cv;
        #pragma unroll
        for (int mi = 0; mi < 2; mi++)
            #pragma unroll
            for (int ni = 0; ni < 8; ni++) {
                __half* p = C + (long long)(rr0 + mi * 16) * N + cc0 + ni * 8;
                *(__half2*)p =
                    __floats2half2_rn(acc[mi][ni][0] * alpha, acc[mi][ni][1] * alpha);
                *(__half2*)(p + 8LL * N) =
                    __floats2half2_rn(acc[mi][ni][2] * alpha, acc[mi][ni][3] * alpha);
            }
    } else if (OUT == 2) {
        float* C = (float*)Cv;
        #pragma unroll
        for (int mi = 0; mi < 2; mi++) {
            const float inv0 = 1.0f / __ldcg(rs + rr0 + mi * 16);
            const float inv1 = 1.0f / __ldcg(rs + rr0 + mi * 16 + 8);
            #pragma unroll
            for (int ni = 0; ni < 8; ni++) {
                float* p = C + (long long)(rr0 + mi * 16) * N + cc0 + ni * 8;
                float2 v0, v1;
                v0.x = acc[mi][ni][0] * inv0; v0.y = acc[mi][ni][1] * inv0;
                v1.x = acc[mi][ni][2] * inv1; v1.y = acc[mi][ni][3] * inv1;
                *(float2*)p = v0;
                *(float2*)(p + 8LL * N) = v1;
            }
        }
    } else {  // OUT == 3: exp epilogue, fp16 write + row-sum atomics
        #pragma unroll
        for (int mi = 0; mi < 2; mi++) {
            float s0 = 0.0f, s1 = 0.0f;
            #pragma unroll
            for (int ni = 0; ni < 8; ni++) {
                float e0 = __expf(acc[mi][ni][0] * alpha);
                float e1 = __expf(acc[mi][ni][1] * alpha);
                float e2 = __expf(acc[mi][ni][2] * alpha);
                float e3 = __expf(acc[mi][ni][3] * alpha);
                __half* q = C2 + (long long)(rr0 + mi * 16) * N + cc0 + ni * 8;
                *(__half2*)q = __floats2half2_rn(e0, e1);
                *(__half2*)(q + 8LL * N) = __floats2half2_rn(e2, e3);
                s0 += e0 + e1;
                s1 += e2 + e3;
            }
            s0 += __shfl_xor_sync(0xFFFFFFFFu, s0, 1);
            s0 += __shfl_xor_sync(0xFFFFFFFFu, s0, 2);
            s1 += __shfl_xor_sync(0xFFFFFFFFu, s1, 1);
            s1 += __shfl_xor_sync(0xFFFFFFFFu, s1, 2);
            if ((lane & 3) == 0) {
                atomicAdd(rsum + rr0 + mi * 16, s0);
                atomicAdd(rsum + rr0 + mi * 16 + 8, s1);
            }
        }
    }
}

// ---------------------------------------------------------------------------
// Mega kernel, fine-grained row-block dependencies.
// Block layout (all deps point to strictly earlier indices):
//   [0, 2304)        proj: per z, 192 QK tiles (m-block-major) then 96 VT
//   [2304, 4352)     scores (z-major, row-block-major; 256 per batch)
//   [4352, 4864)     norm stripes (z,by,cs)  -- overlap with later scores
//   [4864, 5632)     AV tiles (z-major)
// Counters: qkrow (target 12), vtrow (target 16), scrow (target 16).
// ---------------------------------------------------------------------------
#define P_TILES 2304
#define S_TILES 2048
#define N_TILES 512
#define TOTAL_TILES 5632

__global__ __launch_bounds__(256, 2) void mega_kernel(
    const __half* __restrict__ Xh, const __half* __restrict__ Wh,
    __half* __restrict__ QK, __half* __restrict__ VT,
    __half* __restrict__ At, float* __restrict__ rowsum,
    float* __restrict__ out, float* __restrict__ attn, float alpha)
{
    const int bx  = blockIdx.x;
    const int tid = threadIdx.x;
    const long long sQK = (long long)SS * 2 * DD;
    const long long sAT = (long long)SS * SS;
    const long long sVT = (long long)DD * SS;
    const long long sOU = (long long)SS * DD;

    if (bx < P_TILES) {
        // ---- Projection phase ----
        const int z = bx / 288;
        const int r = bx % 288;
        if (r < 192) {
            const int nyg = z * 16 + r / 12;   // global m-block 0..127
            const int nx  = r % 12;
            gemm_body<1>(Xh, Wh, QK, 2 * DD, DD, DD, DD, 1.0f,
                         nyg * 128, nx * 128, nullptr, nullptr, nullptr);
            __threadfence();
            __syncthreads();
            if (tid == 0) atomicAdd(&g_cnt_qkrow[nyg], 1);
        } else {
            const int rv = r - 192;
            const int nx = rv % 16;            // s-tile
            const int ny = rv / 16;            // d-block 0..5
            gemm_body<1>(Wh + 2LL * DD * DD, Xh + (long long)z * SS * DD,
                         VT + (long long)z * sVT,
                         SS, DD, DD, DD, 1.0f, ny * 128, nx * 128,
                         nullptr, nullptr, nullptr);
            __threadfence();
            __syncthreads();
            if (tid == 0) atomicAdd(&g_cnt_vtrow[z * 6 + ny], 1);
        }
    } else if (bx < P_TILES + S_TILES) {
        // ---- Scores phase ----
        const int s = bx - P_TILES;
        const int z  = s >> 8;
        const int r  = s & 255;
        const int by = r >> 4;
        const int nxx = r & 15;
        if (tid == 0) {
            spin_until(&g_cnt_qkrow[z * 16 + by], 12);
            spin_until(&g_cnt_qkrow[z * 16 + nxx], 12);
        }
        __syncthreads();
        gemm_body<3>(QK + z * sQK, QK + z * sQK + DD, nullptr,
                     SS, DD, 2 * DD, 2 * DD, alpha,
                     by * 128, nxx * 128,
                     nullptr, At + z * sAT, rowsum + z * SS);
        __threadfence();
        __syncthreads();
        if (tid == 0) atomicAdd(&g_cnt_scrow[z * 16 + by], 1);
    } else if (bx < P_TILES + S_TILES + N_TILES) {
        // ---- Norm stripes (DRAM-bound; overlap with later scores) ----
        const int j  = bx - P_TILES - S_TILES;
        const int z  = j >> 6;
        const int r  = j & 63;
        const int by = r >> 2;
        const int cs = r & 3;
        if (tid == 0) spin_until(&g_cnt_scrow[z * 16 + by], 16);
        __syncthreads();

        const int warp = tid >> 5;
        const int lane = tid & 31;
        const float* rsb = rowsum + z * SS + by * 128;
        const __half* Ab = At + z * sAT;
        float* Ob = attn + z * sAT;

        for (int rr = warp; rr < 128; rr += 8) {
            const long long row = (long long)by * 128 + rr;
            const float inv = 1.0f / __ldcg(rsb + rr);
            const uint2* src = (const uint2*)(Ab + row * SS + cs * 512);
            float4*      dst = (float4*)(Ob + row * SS + cs * 512);
            #pragma unroll
            for (int c = lane; c < 128; c += 32) {
                uint2 u = __ldcg(src + c);
                __half2 h01 = *reinterpret_cast<__half2*>(&u.x);
                __half2 h23 = *reinterpret_cast<__half2*>(&u.y);
                float2 f01 = __half22float2(h01);
                float2 f23 = __half22float2(h23);
                float4 w;
                w.x = f01.x * inv; w.y = f01.y * inv;
                w.z = f23.x * inv; w.w = f23.y * inv;
                dst[c] = w;
            }
        }
    } else {
        // ---- AV phase ----
        const int v = bx - P_TILES - S_TILES - N_TILES;
        const int z = v / 96;
        const int r = v % 96;
        const int nx = r % 6;     // d-block
        const int ny = r / 6;     // s row-block
        if (tid == 0) {
            spin_until(&g_cnt_scrow[z * 16 + ny], 16);
            spin_until(&g_cnt_vtrow[z * 6 + nx], 16);
        }
        __syncthreads();
        gemm_body<2>(At + z * sAT, VT + z * sVT, out + z * sOU,
                     DD, SS, SS, SS, 1.0f,
                     ny * 128, nx * 128,
                     rowsum + z * SS, nullptr, nullptr);
    }
}

extern "C" void kernel_launch(void* const* d_in, const int* in_sizes, int n_in,
                              void* d_out, int out_size)
{
    const float* x  = (const float*)d_in[0];
    const float* Wq = (const float*)d_in[1];
    const float* Wk = (const float*)d_in[2];
    const float* Wv = (const float*)d_in[3];

    float* out  = (float*)d_out;                   // weighted_values [B,S,D]
    float* attn = out + (long long)BB * SS * DD;   // attention_weights [B,S,S]

    __half *QK, *VT, *Xh, *Wh, *At;
    float* rowsum;
    cudaGetSymbolAddress((void**)&QK, g_QK);
    cudaGetSymbolAddress((void**)&VT, g_VT);
    cudaGetSymbolAddress((void**)&Xh, g_Xh);
    cudaGetSymbolAddress((void**)&Wh, g_Wh);
    cudaGetSymbolAddress((void**)&At, g_At);
    cudaGetSymbolAddress((void**)&rowsum, g_rowsum);

    cudaFuncSetAttribute(mega_kernel,
                         cudaFuncAttributeMaxDynamicSharedMemorySize, DYN_SMEM);

    dim3 blk(256);
    const float alpha = 1.0f / sqrtf((float)DD);

    // fp32 -> fp16 for x/W + rowsum & counter zeroing (one launch).
    {
        int n4x = BB * SS * DD / 4;
        int n4w = DD * DD / 4;
        int tot = n4x + 3 * n4w;
        cvt_all_kernel<<<(tot + 255) / 256, blk>>>(
            (const float4*)x, (const float4*)Wq, (const float4*)Wk,
            (const float4*)Wv, (uint2*)Xh, (uint2*)Wh, (float4*)rowsum,
            n4x, n4w);
    }

    // Everything else: one launch with fine-grained counter dependencies.
    mega_kernel<<<TOTAL_TILES, blk, DYN_SMEM>>>(
        Xh, Wh, QK, VT, At, rowsum, out, attn, alpha);
}

// round 16
// speedup vs baseline: 1.0341x; 1.0341x over previous
#include <cuda_runtime.h>
#include <cuda_fp16.h>
#include <math.h>
#include <stdint.h>

#define BB 8
#define SS 2048
#define DD 768

// Scratch (allocation-free __device__ globals). fp16 operands everywhere.
__device__ __half g_QK[BB * SS * (2 * DD)];  // Q|K interleaved: [B*S, 1536]
__device__ __half g_VT[BB * DD * SS];        // V transposed per batch: [B][D][S]
__device__ __half g_Xh[BB * SS * DD];        // x in fp16
__device__ __half g_Wh[3 * DD * DD];         // Wq|Wk|Wv in fp16
__device__ __half g_At[BB * SS * SS];        // exp(scores) in fp16 (unnormalized)
__device__ float  g_rowsum[BB * SS];         // per-row sums of exp(scores)
// Fine-grained completion counters:
__device__ int    g_cnt_qkrow[BB * 16];      // per QK m-block (target 12)
__device__ int    g_cnt_vtrow[BB * 6];       // per VT d-block (target 16)
__device__ int    g_cnt_scrow[BB * 16];      // per scores row-block (target 16)

__device__ __forceinline__ uint32_t swz(uint32_t byte) {
    return byte ^ ((byte >> 3) & 0x70);
}
__device__ __forceinline__ void ldsm4(uint32_t& r0, uint32_t& r1,
                                      uint32_t& r2, uint32_t& r3, uint32_t addr) {
    asm volatile("ldmatrix.sync.aligned.m8n8.x4.shared.b16 {%0,%1,%2,%3}, [%4];"
                 : "=r"(r0), "=r"(r1), "=r"(r2), "=r"(r3) : "r"(addr));
}
__device__ __forceinline__ void mma16(float* c, const uint32_t* a,
                                      uint32_t b0, uint32_t b1) {
    asm volatile(
        "mma.sync.aligned.m16n8k16.row.col.f32.f16.f16.f32 "
        "{%0,%1,%2,%3}, {%4,%5,%6,%7}, {%8,%9}, {%0,%1,%2,%3};"
        : "+f"(c[0]), "+f"(c[1]), "+f"(c[2]), "+f"(c[3])
        : "r"(a[0]), "r"(a[1]), "r"(a[2]), "r"(a[3]), "r"(b0), "r"(b1));
}
__device__ __forceinline__ void cp16(uint32_t dst, const void* src) {
    asm volatile("cp.async.cg.shared.global [%0], [%1], 16;" :: "r"(dst), "l"(src));
}
__device__ __forceinline__ void cp_commit() {
    asm volatile("cp.async.commit_group;" ::: "memory");
}
__device__ __forceinline__ void cp_wait1() {
    asm volatile("cp.async.wait_group 1;" ::: "memory");
}
__device__ __forceinline__ void spin_until(int* cnt, int target) {
    while (atomicAdd(cnt, 0) < target) __nanosleep(128);
}

// ---------------------------------------------------------------------------
// Fused elementwise fp32 -> fp16 over x, Wq, Wk, Wv + rowsum/counter zeroing.
// ---------------------------------------------------------------------------
__device__ __forceinline__ uint2 cvt4(float4 v) {
    __half2 h01 = __floats2half2_rn(v.x, v.y);
    __half2 h23 = __floats2half2_rn(v.z, v.w);
    uint2 u;
    u.x = *reinterpret_cast<uint32_t*>(&h01);
    u.y = *reinterpret_cast<uint32_t*>(&h23);
    return u;
}
__global__ __launch_bounds__(256) void cvt_all_kernel(
    const float4* __restrict__ x,
    const float4* __restrict__ wq, const float4* __restrict__ wk,
    const float4* __restrict__ wv,
    uint2* __restrict__ xh, uint2* __restrict__ wh,
    float4* __restrict__ rz, int n4x, int n4w)
{
    int i = blockIdx.x * 256 + threadIdx.x;
    if (i < (BB * SS) / 4)
        rz[i] = make_float4(0.f, 0.f, 0.f, 0.f);
    if (i < BB * 16) { g_cnt_qkrow[i] = 0; g_cnt_scrow[i] = 0; }
    if (i < BB * 6)  { g_cnt_vtrow[i] = 0; }
    if (i < n4x) {
        xh[i] = cvt4(x[i]);
    } else {
        int j = i - n4x;
        if (j < n4w)               wh[j] = cvt4(wq[j]);
        else if (j < 2 * n4w)      wh[j] = cvt4(wk[j - n4w]);
        else if (j < 3 * n4w)      wh[j] = cvt4(wv[j - 2 * n4w]);
    }
}

// ---------------------------------------------------------------------------
// GEMM body (R7-validated mainloop): TN fp16, acc = sum_k A[m,k]*B[n,k].
// Block tile 128x128, K-chunks of 64 (128B SW128 rows), 3-stage cp.async,
// 8 warps (4m x 2n), warp tile 32x64 of m16n8k16 MMAs.
// Epilogues:
//   OUT=1 : C fp16 = acc*alpha                         (projections)
//   OUT=2 : C fp32 = acc * (1/rs[row])                 (AV)
//   OUT=3 : e=expf(acc*alpha); C2 fp16 = e; atomicAdd rsum[row]  (scores)
// ---------------------------------------------------------------------------
#define CK 64
#define STG_BYTES 32768            // A 16KB + B 16KB
#define DYN_SMEM  (3 * STG_BYTES)  // 98304; 2 CTAs/SM

template <int OUT>
__device__ __forceinline__ void gemm_body(
    const __half* __restrict__ A, const __half* __restrict__ B,
    void* __restrict__ Cv, int N, int K, int lda, int ldb,
    float alpha, int m0, int n0,
    const float* __restrict__ rs, __half* __restrict__ C2,
    float* __restrict__ rsum)
{
    extern __shared__ __align__(1024) uint8_t dynsm[];

    const int tid  = threadIdx.x;
    const int lane = tid & 31;
    const int warp = tid >> 5;
    const int wm   = warp >> 1;
    const int wn   = warp & 1;

    const uint32_t smbase = (uint32_t)__cvta_generic_to_shared(dynsm);

    const int r0  = tid >> 3;
    const int gg  = tid & 7;
    const uint32_t g16 = (uint32_t)gg * 16;

    const __half* pa[4]; uint32_t oa[4];
    const __half* pb[4]; uint32_t ob[4];
    #pragma unroll
    for (int j = 0; j < 4; j++) {
        int row = r0 + 32 * j;
        pa[j] = A + (long long)(m0 + row) * lda + gg * 8;
        oa[j] = swz((uint32_t)row * 128 + g16);
        pb[j] = B + (long long)(n0 + row) * ldb + gg * 8;
        ob[j] = swz((uint32_t)row * 128 + g16) + 16384;
    }

    const int KT = K / CK;

    #define FILL(t) do {                                          \
        uint32_t sb = smbase + ((t) % 3) * STG_BYTES;             \
        int ko = (t) * CK;                                        \
        _Pragma("unroll")                                         \
        for (int j = 0; j < 4; j++) {                             \
            cp16(sb + oa[j], pa[j] + ko);                         \
            cp16(sb + ob[j], pb[j] + ko);                         \
        }                                                         \
    } while (0)

    FILL(0); cp_commit();
    FILL(1); cp_commit();

    float acc[2][8][4] = {};

    const int lrow = (lane & 7) + ((lane >> 3) & 1) * 8;
    const uint32_t glo = (uint32_t)(lane >> 4) * 16;
    uint32_t aoff[2], boff[4];
    #pragma unroll
    for (int mi = 0; mi < 2; mi++)
        aoff[mi] = swz((uint32_t)((wm * 32 + mi * 16 + lrow) * 128)) ^ glo;
    #pragma unroll
    for (int l = 0; l < 4; l++)
        boff[l] = (swz((uint32_t)((wn * 64 + l * 16 + lrow) * 128)) ^ glo) + 16384;

    for (int i = 0; i < KT; i++) {
        cp_wait1();
        __syncthreads();
        if (i + 2 < KT) FILL(i + 2);
        cp_commit();

        const uint32_t stage = smbase + (i % 3) * STG_BYTES;

        #pragma unroll
        for (int ks = 0; ks < 4; ks++) {
            const uint32_t gx = (uint32_t)(ks * 32);
            uint32_t a[2][4], b[4][4];
            #pragma unroll
            for (int mi = 0; mi < 2; mi++)
                ldsm4(a[mi][0], a[mi][1], a[mi][2], a[mi][3],
                      stage + (aoff[mi] ^ gx));
            #pragma unroll
            for (int l = 0; l < 4; l++)
                ldsm4(b[l][0], b[l][1], b[l][2], b[l][3],
                      stage + (boff[l] ^ gx));
            #pragma unroll
            for (int mi = 0; mi < 2; mi++)
                #pragma unroll
                for (int j = 0; j < 8; j++) {
                    const int l = j >> 1, o = j & 1;
                    mma16(acc[mi][j], a[mi], b[l][o], b[l][o + 2]);
                }
        }
    }
    #undef FILL

    const int rr0 = m0 + wm * 32 + (lane >> 2);
    const int cc0 = n0 + wn * 64 + (lane & 3) * 2;

    if (OUT == 1) {
        __half* C = (__half*)Cv;
        #pragma unroll
        for (int mi = 0; mi < 2; mi++)
            #pragma unroll
            for (int ni = 0; ni < 8; ni++) {
                __half* p = C + (long long)(rr0 + mi * 16) * N + cc0 + ni * 8;
                *(__half2*)p =
                    __floats2half2_rn(acc[mi][ni][0] * alpha, acc[mi][ni][1] * alpha);
                *(__half2*)(p + 8LL * N) =
                    __floats2half2_rn(acc[mi][ni][2] * alpha, acc[mi][ni][3] * alpha);
            }
    } else if (OUT == 2) {
        float* C = (float*)Cv;
        #pragma unroll
        for (int mi = 0; mi < 2; mi++) {
            const float inv0 = 1.0f / __ldcg(rs + rr0 + mi * 16);
            const float inv1 = 1.0f / __ldcg(rs + rr0 + mi * 16 + 8);
            #pragma unroll
            for (int ni = 0; ni < 8; ni++) {
                float* p = C + (long long)(rr0 + mi * 16) * N + cc0 + ni * 8;
                float2 v0, v1;
                v0.x = acc[mi][ni][0] * inv0; v0.y = acc[mi][ni][1] * inv0;
                v1.x = acc[mi][ni][2] * inv1; v1.y = acc[mi][ni][3] * inv1;
                *(float2*)p = v0;
                *(float2*)(p + 8LL * N) = v1;
            }
        }
    } else {  // OUT == 3: exp epilogue, fp16 write + row-sum atomics
        #pragma unroll
        for (int mi = 0; mi < 2; mi++) {
            float s0 = 0.0f, s1 = 0.0f;
            #pragma unroll
            for (int ni = 0; ni < 8; ni++) {
                float e0 = __expf(acc[mi][ni][0] * alpha);
                float e1 = __expf(acc[mi][ni][1] * alpha);
                float e2 = __expf(acc[mi][ni][2] * alpha);
                float e3 = __expf(acc[mi][ni][3] * alpha);
                __half* q = C2 + (long long)(rr0 + mi * 16) * N + cc0 + ni * 8;
                *(__half2*)q = __floats2half2_rn(e0, e1);
                *(__half2*)(q + 8LL * N) = __floats2half2_rn(e2, e3);
                s0 += e0 + e1;
                s1 += e2 + e3;
            }
            s0 += __shfl_xor_sync(0xFFFFFFFFu, s0, 1);
            s0 += __shfl_xor_sync(0xFFFFFFFFu, s0, 2);
            s1 += __shfl_xor_sync(0xFFFFFFFFu, s1, 1);
            s1 += __shfl_xor_sync(0xFFFFFFFFu, s1, 2);
            if ((lane & 3) == 0) {
                atomicAdd(rsum + rr0 + mi * 16, s0);
                atomicAdd(rsum + rr0 + mi * 16 + 8, s1);
            }
        }
    }
}

// ---------------------------------------------------------------------------
// Mega kernel: fine-grained row-block dependencies + 3:2 AV:norm interleave.
// Block layout (all deps point to strictly earlier indices):
//   [0, 2304)     proj: per z, 192 QK tiles (m-block-major) then 96 VT
//   [2304, 4352)  scores (z-major, row-block-major; 256 per batch)
//   [4352, 5632)  AV + norm, 3:2 interleave per batch (160 per batch)
// Counters: qkrow (target 12), vtrow (target 16), scrow (target 16).
// ---------------------------------------------------------------------------
#define P_TILES 2304
#define S_TILES 2048
#define TOTAL_TILES 5632

__global__ __launch_bounds__(256, 2) void mega_kernel(
    const __half* __restrict__ Xh, const __half* __restrict__ Wh,
    __half* __restrict__ QK, __half* __restrict__ VT,
    __half* __restrict__ At, float* __restrict__ rowsum,
    float* __restrict__ out, float* __restrict__ attn, float alpha)
{
    const int bx  = blockIdx.x;
    const int tid = threadIdx.x;
    const long long sQK = (long long)SS * 2 * DD;
    const long long sAT = (long long)SS * SS;
    const long long sVT = (long long)DD * SS;
    const long long sOU = (long long)SS * DD;

    if (bx < P_TILES) {
        // ---- Projection phase ----
        const int z = bx / 288;
        const int r = bx % 288;
        if (r < 192) {
            const int nyg = z * 16 + r / 12;   // global m-block 0..127
            const int nx  = r % 12;
            gemm_body<1>(Xh, Wh, QK, 2 * DD, DD, DD, DD, 1.0f,
                         nyg * 128, nx * 128, nullptr, nullptr, nullptr);
            __threadfence();
            __syncthreads();
            if (tid == 0) atomicAdd(&g_cnt_qkrow[nyg], 1);
        } else {
            const int rv = r - 192;
            const int nx = rv % 16;            // s-tile
            const int ny = rv / 16;            // d-block 0..5
            gemm_body<1>(Wh + 2LL * DD * DD, Xh + (long long)z * SS * DD,
                         VT + (long long)z * sVT,
                         SS, DD, DD, DD, 1.0f, ny * 128, nx * 128,
                         nullptr, nullptr, nullptr);
            __threadfence();
            __syncthreads();
            if (tid == 0) atomicAdd(&g_cnt_vtrow[z * 6 + ny], 1);
        }
    } else if (bx < P_TILES + S_TILES) {
        // ---- Scores phase ----
        const int s = bx - P_TILES;
        const int z  = s >> 8;
        const int r  = s & 255;
        const int by = r >> 4;
        const int nxx = r & 15;
        if (tid == 0) {
            spin_until(&g_cnt_qkrow[z * 16 + by], 12);
            spin_until(&g_cnt_qkrow[z * 16 + nxx], 12);
        }
        __syncthreads();
        gemm_body<3>(QK + z * sQK, QK + z * sQK + DD, nullptr,
                     SS, DD, 2 * DD, 2 * DD, alpha,
                     by * 128, nxx * 128,
                     nullptr, At + z * sAT, rowsum + z * SS);
        __threadfence();
        __syncthreads();
        if (tid == 0) atomicAdd(&g_cnt_scrow[z * 16 + by], 1);
    } else {
        // ---- AV + norm phase, 3:2 interleave ----
        const int v = bx - P_TILES - S_TILES;
        const int z = v / 160;
        const int r = v % 160;
        const int grp = r / 5, rem = r % 5;
        if (rem < 3) {
            // AV tile i in [0,96): nx = i%6 (d-block), ny = i/6 (s row-block)
            const int i  = grp * 3 + rem;
            const int nx = i % 6;
            const int ny = i / 6;
            if (tid == 0) {
                spin_until(&g_cnt_scrow[z * 16 + ny], 16);
                spin_until(&g_cnt_vtrow[z * 6 + nx], 16);
            }
            __syncthreads();
            gemm_body<2>(At + z * sAT, VT + z * sVT, out + z * sOU,
                         DD, SS, SS, SS, 1.0f,
                         ny * 128, nx * 128,
                         rowsum + z * SS, nullptr, nullptr);
        } else {
            // Norm stripe j in [0,64): by = j>>2, cs = j&3
            const int j  = grp * 2 + (rem - 3);
            const int by = j >> 2;
            const int cs = j & 3;
            if (tid == 0) spin_until(&g_cnt_scrow[z * 16 + by], 16);
            __syncthreads();

            const int warp = tid >> 5;
            const int lane = tid & 31;
            const float* rsb = rowsum + z * SS + by * 128;
            const __half* Ab = At + z * sAT;
            float* Ob = attn + z * sAT;

            for (int rr = warp; rr < 128; rr += 8) {
                const long long row = (long long)by * 128 + rr;
                const float inv = 1.0f / __ldcg(rsb + rr);
                const uint2* src = (const uint2*)(Ab + row * SS + cs * 512);
                float4*      dst = (float4*)(Ob + row * SS + cs * 512);
                #pragma unroll
                for (int c = lane; c < 128; c += 32) {
                    uint2 u = __ldcg(src + c);
                    __half2 h01 = *reinterpret_cast<__half2*>(&u.x);
                    __half2 h23 = *reinterpret_cast<__half2*>(&u.y);
                    float2 f01 = __half22float2(h01);
                    float2 f23 = __half22float2(h23);
                    float4 w;
                    w.x = f01.x * inv; w.y = f01.y * inv;
                    w.z = f23.x * inv; w.w = f23.y * inv;
                    dst[c] = w;
                }
            }
        }
    }
}

extern "C" void kernel_launch(void* const* d_in, const int* in_sizes, int n_in,
                              void* d_out, int out_size)
{
    const float* x  = (const float*)d_in[0];
    const float* Wq = (const float*)d_in[1];
    const float* Wk = (const float*)d_in[2];
    const float* Wv = (const float*)d_in[3];

    float* out  = (float*)d_out;                   // weighted_values [B,S,D]
    float* attn = out + (long long)BB * SS * DD;   // attention_weights [B,S,S]

    __half *QK, *VT, *Xh, *Wh, *At;
    float* rowsum;
    cudaGetSymbolAddress((void**)&QK, g_QK);
    cudaGetSymbolAddress((void**)&VT, g_VT);
    cudaGetSymbolAddress((void**)&Xh, g_Xh);
    cudaGetSymbolAddress((void**)&Wh, g_Wh);
    cudaGetSymbolAddress((void**)&At, g_At);
    cudaGetSymbolAddress((void**)&rowsum, g_rowsum);

    cudaFuncSetAttribute(mega_kernel,
                         cudaFuncAttributeMaxDynamicSharedMemorySize, DYN_SMEM);

    dim3 blk(256);
    const float alpha = 1.0f / sqrtf((float)DD);

    // fp32 -> fp16 for x/W + rowsum & counter zeroing (one launch).
    {
        int n4x = BB * SS * DD / 4;
        int n4w = DD * DD / 4;
        int tot = n4x + 3 * n4w;
        cvt_all_kernel<<<(tot + 255) / 256, blk>>>(
            (const float4*)x, (const float4*)Wq, (const float4*)Wk,
            (const float4*)Wv, (uint2*)Xh, (uint2*)Wh, (float4*)rowsum,
            n4x, n4w);
    }

    // Everything else: one launch, fine-grained deps + 3:2 interleave.
    mega_kernel<<<TOTAL_TILES, blk, DYN_SMEM>>>(
        Xh, Wh, QK, VT, At, rowsum, out, attn, alpha);
}